// round 9
// baseline (speedup 1.0000x reference)
#include <cuda_runtime.h>
#include <cuda_bf16.h>
#include <math.h>
#include <stdint.h>

#define NNODES 16000
#define DIN    256
#define HD     256
#define NH     8
#define NEDGES 256000

// ---------------- device scratch ----------------
__device__ float g_q[NNODES * HD];
__device__ float g_k[NNODES * HD];
__device__ float g_v[NNODES * HD];
__device__ float g_wV[NNODES * HD];
__device__ float g_z[NNODES * NH];
// transposed bf16 weight images: [mat][n=256][k=256]; mat: 0=Wq 1=Wk 2=Wv 3=We
__device__ __nv_bfloat16 g_Bth[4][256 * 256];
__device__ __nv_bfloat16 g_Btl[4][256 * 256];

// ---------------- helpers ----------------
__device__ __forceinline__ void mma16816(float* d, const uint32_t* a, const uint32_t* b) {
    asm volatile(
        "mma.sync.aligned.m16n8k16.row.col.f32.bf16.bf16.f32 "
        "{%0,%1,%2,%3}, {%4,%5,%6,%7}, {%8,%9}, {%0,%1,%2,%3};"
        : "+f"(d[0]), "+f"(d[1]), "+f"(d[2]), "+f"(d[3])
        : "r"(a[0]), "r"(a[1]), "r"(a[2]), "r"(a[3]), "r"(b[0]), "r"(b[1]));
}
__device__ __forceinline__ uint32_t smem_u32(const void* p) {
    uint32_t a;
    asm("{ .reg .u64 t; cvta.to.shared.u64 t, %1; cvt.u32.u64 %0, t; }" : "=r"(a) : "l"(p));
    return a;
}
__device__ __forceinline__ void cp_async16(uint32_t dst, const void* src) {
    asm volatile("cp.async.cg.shared.global [%0], [%1], 16;" :: "r"(dst), "l"(src));
}
#define CP_COMMIT asm volatile("cp.async.commit_group;" ::: "memory")
#define CP_WAIT0  asm volatile("cp.async.wait_group 0;" ::: "memory")
#define LDSM4(r, addr) \
    asm volatile("ldmatrix.sync.aligned.m8n8.x4.shared.b16 {%0,%1,%2,%3}, [%4];" \
        : "=r"((r)[0]), "=r"((r)[1]), "=r"((r)[2]), "=r"((r)[3]) : "r"(addr))

// SMEM layout (bytes). A/B tiles use 80B rows (conflict-free ldsm).
// A: 128 rows x 32 k (hi 10240 + lo 10240) x 2 bufs
// B: 64 n    x 32 k (hi 5120  + lo 5120)  x 2 bufs
#define SM_SRC   0
#define SM_DST   512
#define SM_DIST  1024
#define SM_AX    1536      // 128*2 floats = 1024
#define SM_A     2560
#define ABUF     20480
#define SM_B     43520
#define BBUF     10240
#define SM_TOTAL 64000

// ---------------------------------------------------------------------------
__global__ void zero_kernel(const float* __restrict__ coords, float* __restrict__ cout) {
    int i = blockIdx.x * blockDim.x + threadIdx.x;
    if (i < NNODES * HD) g_wV[i] = 0.0f;
    if (i < NNODES * NH) g_z[i] = 0.0f;
    if (i < NNODES * 3)  cout[i] = coords[i];
}

// ---------------------------------------------------------------------------
// Weight prep: W[k][n] fp32 -> g_Bt{h,l}[mat][n][k] bf16 (hi/lo split).
// ---------------------------------------------------------------------------
__global__ void prep_weights(const float* __restrict__ Wq, const float* __restrict__ Wk,
                             const float* __restrict__ Wv, const float* __restrict__ We) {
    int t = blockIdx.x * blockDim.x + threadIdx.x;
    if (t >= 4 * 256 * 32) return;
    int mat = t >> 13;
    int rem = t & 8191;
    int n   = rem >> 5;
    int ku  = rem & 31;
    const float* W = mat == 0 ? Wq : mat == 1 ? Wk : mat == 2 ? Wv : We;
    uint32_t h[4], l[4];
    #pragma unroll
    for (int p = 0; p < 4; ++p) {
        float f0 = W[(ku * 8 + 2 * p) * HD + n];
        float f1 = W[(ku * 8 + 2 * p + 1) * HD + n];
        __nv_bfloat162 hh = __floats2bfloat162_rn(f0, f1);
        float l0 = f0 - __bfloat162float(hh.x);
        float l1 = f1 - __bfloat162float(hh.y);
        __nv_bfloat162 ll = __floats2bfloat162_rn(l0, l1);
        h[p] = *(uint32_t*)&hh;
        l[p] = *(uint32_t*)&ll;
    }
    *(uint4*)&g_Bth[mat][n * 256 + ku * 8] = make_uint4(h[0], h[1], h[2], h[3]);
    *(uint4*)&g_Btl[mat][n * 256 + ku * 8] = make_uint4(l[0], l[1], l[2], l[3]);
}

// ---------------------------------------------------------------------------
// A convert+store: 256 threads, each 16 k-floats of one row.
// ---------------------------------------------------------------------------
__device__ __forceinline__ void convert_store_A(char* smem, int buf, int tid,
                                                const float4* f) {
    int r = tid >> 1, u = tid & 1;
    const float* fv = (const float*)f;
    uint32_t h[8], l[8];
    #pragma unroll
    for (int p = 0; p < 8; ++p) {
        __nv_bfloat162 hh = __floats2bfloat162_rn(fv[2 * p], fv[2 * p + 1]);
        float l0 = fv[2 * p] - __bfloat162float(hh.x);
        float l1 = fv[2 * p + 1] - __bfloat162float(hh.y);
        __nv_bfloat162 ll = __floats2bfloat162_rn(l0, l1);
        h[p] = *(uint32_t*)&hh;
        l[p] = *(uint32_t*)&ll;
    }
    char* base = smem + SM_A + buf * ABUF + r * 80 + u * 32;
    *(uint4*)(base)              = make_uint4(h[0], h[1], h[2], h[3]);
    *(uint4*)(base + 16)         = make_uint4(h[4], h[5], h[6], h[7]);
    *(uint4*)(base + 10240)      = make_uint4(l[0], l[1], l[2], l[3]);
    *(uint4*)(base + 10240 + 16) = make_uint4(l[4], l[5], l[6], l[7]);
}

// ---------------------------------------------------------------------------
// GEMM mainloop: acc[2][4][4] += split-bf16( A[m0:128, :256] @ W[n0:64]^T )
// 256 threads, 8 warps (4 m x 2 n); warp tile 32 x 32. Double-buffered.
// ---------------------------------------------------------------------------
__device__ __forceinline__ void gemm_tile(char* smem, uint32_t sb,
                                          const float* __restrict__ A, int m0,
                                          int mat, int n0, int tid, float acc[2][4][4]) {
    int lane = tid & 31, w = tid >> 5;
    int warp_m = w & 3, warp_n = w >> 2;
    const __nv_bfloat16* Bh = g_Bth[mat] + (size_t)n0 * 256;
    const __nv_bfloat16* Bl = g_Btl[mat] + (size_t)n0 * 256;
    int r = tid >> 1, u = tid & 1;

    uint32_t aRow = (uint32_t)(warp_m * 32 + (lane & 7) + ((lane >> 3) & 1) * 8);
    uint32_t aOff = aRow * 80 + ((lane >> 4) & 1) * 16;
    uint32_t bRow = (uint32_t)(warp_n * 32 + (lane & 7) + ((lane >> 4) & 1) * 8);
    uint32_t bOff = bRow * 80 + ((lane >> 3) & 1) * 16;

    // prologue: chunk 0
    {
        float4 f[4];
        const float4* src = (const float4*)(A + (size_t)(m0 + r) * DIN + u * 16);
        f[0] = src[0]; f[1] = src[1]; f[2] = src[2]; f[3] = src[3];
        {
            int n = tid >> 2, uu = tid & 3;      // 64 n x 4 units
            cp_async16(sb + SM_B + n * 80 + uu * 16,        &Bh[n * 256 + uu * 8]);
            cp_async16(sb + SM_B + 5120 + n * 80 + uu * 16, &Bl[n * 256 + uu * 8]);
        }
        CP_COMMIT;
        convert_store_A(smem, 0, tid, f);
        CP_WAIT0;
        __syncthreads();
    }

    for (int kc = 0; kc < 8; ++kc) {
        int cur = kc & 1, nxt = cur ^ 1;
        float4 f[4];
        if (kc < 7) {
            const float4* src = (const float4*)(A + (size_t)(m0 + r) * DIN + (kc + 1) * 32 + u * 16);
            f[0] = src[0]; f[1] = src[1]; f[2] = src[2]; f[3] = src[3];
            {
                int n = tid >> 2, uu = tid & 3;
                cp_async16(sb + SM_B + nxt * BBUF + n * 80 + uu * 16,
                           &Bh[n * 256 + (kc + 1) * 32 + uu * 8]);
                cp_async16(sb + SM_B + nxt * BBUF + 5120 + n * 80 + uu * 16,
                           &Bl[n * 256 + (kc + 1) * 32 + uu * 8]);
            }
            CP_COMMIT;
        }

        uint32_t aBase = sb + SM_A + cur * ABUF + aOff;
        uint32_t bBase = sb + SM_B + cur * BBUF + bOff;
        #pragma unroll
        for (int ks = 0; ks < 2; ++ks) {
            uint32_t ah[2][4], al[2][4];
            LDSM4(ah[0], aBase + ks * 32);
            LDSM4(ah[1], aBase + ks * 32 + 1280);            // +16 rows
            LDSM4(al[0], aBase + ks * 32 + 10240);
            LDSM4(al[1], aBase + ks * 32 + 10240 + 1280);
            uint32_t bh[2][4], bl[2][4];
            #pragma unroll
            for (int pr = 0; pr < 2; ++pr) {
                LDSM4(bh[pr], bBase + ks * 32 + pr * 1280);
                LDSM4(bl[pr], bBase + ks * 32 + pr * 1280 + 5120);
            }
            #pragma unroll
            for (int pr = 0; pr < 2; ++pr) {
                #pragma unroll
                for (int sub = 0; sub < 2; ++sub) {
                    int nf = pr * 2 + sub;
                    uint32_t b2h[2] = {bh[pr][2 * sub], bh[pr][2 * sub + 1]};
                    uint32_t b2l[2] = {bl[pr][2 * sub], bl[pr][2 * sub + 1]};
                    #pragma unroll
                    for (int mf = 0; mf < 2; ++mf) {
                        mma16816(acc[mf][nf], ah[mf], b2h);
                        mma16816(acc[mf][nf], al[mf], b2h);
                        mma16816(acc[mf][nf], ah[mf], b2l);
                    }
                }
            }
        }

        if (kc < 7) {
            convert_store_A(smem, nxt, tid, f);
            CP_WAIT0;
            __syncthreads();
        }
    }
}

// ---------------------------------------------------------------------------
// QKV GEMM. grid (125, 3, 4), 256 threads.
// ---------------------------------------------------------------------------
__global__ __launch_bounds__(256, 3) void qkv_mm(const float* __restrict__ x) {
    extern __shared__ char smem[];
    uint32_t sb = smem_u32(smem);
    int tid = threadIdx.x;
    int m0 = blockIdx.x * 128;
    int mat = blockIdx.y;
    int n0 = blockIdx.z * 64;

    float acc[2][4][4];
    #pragma unroll
    for (int mf = 0; mf < 2; ++mf)
        #pragma unroll
        for (int nf = 0; nf < 4; ++nf)
            #pragma unroll
            for (int p = 0; p < 4; ++p) acc[mf][nf][p] = 0.0f;

    gemm_tile(smem, sb, x, m0, mat, n0, tid, acc);

    int lane = tid & 31, w = tid >> 5;
    int warp_m = w & 3, warp_n = w >> 2;
    int qrow = lane >> 2, qcol = lane & 3;
    float* out = mat == 0 ? g_q : mat == 1 ? g_k : g_v;

    #pragma unroll
    for (int mf = 0; mf < 2; ++mf) {
        int r0 = m0 + warp_m * 32 + mf * 16 + qrow;
        #pragma unroll
        for (int nf = 0; nf < 4; ++nf) {
            int c = n0 + warp_n * 32 + nf * 8 + qcol * 2;
            *(float2*)(out + (size_t)r0 * HD + c)       = make_float2(acc[mf][nf][0], acc[mf][nf][1]);
            *(float2*)(out + (size_t)(r0 + 8) * HD + c) = make_float2(acc[mf][nf][2], acc[mf][nf][3]);
        }
    }
}

// ---------------------------------------------------------------------------
// Edge GEMM + fused attention epilogue. grid (2000, 4), 256 threads.
// Each CTA: 128 edges x 64 cols (2 heads); each warp's 32 cols = 1 head.
// ---------------------------------------------------------------------------
__global__ __launch_bounds__(256, 3) void edge_mm(const float* __restrict__ edge_attr,
                                                  const int* __restrict__ ei,
                                                  const float* __restrict__ coords,
                                                  const float* __restrict__ We,
                                                  float* __restrict__ eout) {
    extern __shared__ char smem[];
    uint32_t sb = smem_u32(smem);
    int tid = threadIdx.x;
    int m0 = blockIdx.x * 128;
    int n0 = blockIdx.y * 64;
    int hbase = n0 >> 5;                        // first of 2 heads in this CTA

    int*   sSrc = (int*)(smem + SM_SRC);
    int*   sDst = (int*)(smem + SM_DST);
    float* sDist = (float*)(smem + SM_DIST);
    float* sAx  = (float*)(smem + SM_AX);       // [128][2]

    if (tid < 128) {
        int s = ei[m0 + tid];
        int d = ei[NEDGES + m0 + tid];
        sSrc[tid] = s; sDst[tid] = d;
        float dx = coords[3 * s + 0] - coords[3 * d + 0];
        float dy = coords[3 * s + 1] - coords[3 * d + 1];
        float dz = coords[3 * s + 2] - coords[3 * d + 2];
        sDist[tid] = 0.1f * sqrtf(dx * dx + dy * dy + dz * dz);
    }
    __syncthreads();

    float acc[2][4][4];
    #pragma unroll
    for (int mf = 0; mf < 2; ++mf)
        #pragma unroll
        for (int nf = 0; nf < 4; ++nf)
            #pragma unroll
            for (int p = 0; p < 4; ++p) acc[mf][nf][p] = 0.0f;

    gemm_tile(smem, sb, edge_attr, m0, 3, n0, tid, acc);

    int lane = tid & 31, w = tid >> 5;
    int warp_m = w & 3, warp_n = w >> 2;
    int qrow = lane >> 2, qcol = lane & 3;
    const float invs = 0.17677669529663687f;   // 1/sqrt(32)

    #pragma unroll
    for (int mf = 0; mf < 2; ++mf) {
        int erow0 = warp_m * 32 + mf * 16 + qrow;
        #pragma unroll
        for (int half = 0; half < 2; ++half) {
            int e = erow0 + 8 * half;
            int src = sSrc[e], dst = sDst[e];
            float de = sDist[e];
            float hsum = 0.0f;
            #pragma unroll
            for (int nf = 0; nf < 4; ++nf) {
                int c = n0 + warp_n * 32 + nf * 8 + qcol * 2;
                float2 kk = *(const float2*)(g_k + (size_t)src * HD + c);
                float2 qq = *(const float2*)(g_q + (size_t)dst * HD + c);
                float2 wl = *(const float2*)(We + (size_t)DIN * HD + c);
                float d0 = acc[mf][nf][2 * half + 0];
                float d1 = acc[mf][nf][2 * half + 1];
                float s0 = fminf(5.0f, fmaxf(-5.0f, kk.x * qq.x * invs));
                float s1 = fminf(5.0f, fmaxf(-5.0f, kk.y * qq.y * invs));
                float a0 = s0 * (d0 + de * wl.x);
                float a1 = s1 * (d1 + de * wl.y);
                *(float2*)(eout + (size_t)(m0 + e) * HD + c) = make_float2(a0, a1);
                hsum += a0 + a1;
            }
            hsum += __shfl_xor_sync(0xffffffffu, hsum, 1);
            hsum += __shfl_xor_sync(0xffffffffu, hsum, 2);
            if (qcol == 0) {
                float ax = expf(fminf(5.0f, fmaxf(-5.0f, hsum)));
                sAx[e * 2 + warp_n] = ax;
                atomicAdd(&g_z[(size_t)dst * NH + hbase + warp_n], ax);
            }
        }
    }
    __syncthreads();

    // scatter wV += v[src] * ax : 256 (edge, local head) pairs over 256 threads
    {
        int e = tid >> 1, lh = tid & 1;
        int src = sSrc[e], dst = sDst[e];
        float ax = sAx[e * 2 + lh];
        int h = hbase + lh;
        const float4* v4 = (const float4*)(g_v + (size_t)src * HD + h * 32);
        float* wv = g_wV + (size_t)dst * HD + h * 32;
        #pragma unroll
        for (int j = 0; j < 8; ++j) {
            float4 vv = v4[j];
            atomicAdd(wv + 4 * j + 0, vv.x * ax);
            atomicAdd(wv + 4 * j + 1, vv.y * ax);
            atomicAdd(wv + 4 * j + 2, vv.z * ax);
            atomicAdd(wv + 4 * j + 3, vv.w * ax);
        }
    }
}

// ---------------------------------------------------------------------------
__global__ void finalize_kernel(float* __restrict__ hout) {
    int i = blockIdx.x * blockDim.x + threadIdx.x;
    if (i < NNODES * HD) {
        int n = i >> 8;
        int h = (i & 255) >> 5;
        hout[i] = g_wV[i] / (g_z[n * NH + h] + 1e-6f);
    }
}

// ---------------------------------------------------------------------------
extern "C" void kernel_launch(void* const* d_in, const int* in_sizes, int n_in,
                              void* d_out, int out_size)
{
    const float* x         = (const float*)d_in[0];
    const float* edge_attr = (const float*)d_in[1];
    const int*   ei        = (const int*)d_in[2];
    const float* coords    = (const float*)d_in[3];
    const float* Wq        = (const float*)d_in[4];
    const float* Wk        = (const float*)d_in[5];
    const float* Wv        = (const float*)d_in[6];
    const float* We        = (const float*)d_in[7];

    float* out  = (float*)d_out;
    float* hout = out;
    float* eout = out + (size_t)NNODES * HD;
    float* cout = eout + (size_t)NEDGES * HD;

    static bool attr_set = false;
    if (!attr_set) {
        cudaFuncSetAttribute(qkv_mm,  cudaFuncAttributeMaxDynamicSharedMemorySize, SM_TOTAL);
        cudaFuncSetAttribute(edge_mm, cudaFuncAttributeMaxDynamicSharedMemorySize, SM_TOTAL);
        attr_set = true;
    }

    zero_kernel<<<(NNODES * HD + 255) / 256, 256>>>(coords, cout);
    prep_weights<<<128, 256>>>(Wq, Wk, Wv, We);
    qkv_mm<<<dim3(125, 3, 4), 256, SM_TOTAL>>>(x);
    edge_mm<<<dim3(2000, 4), 256, SM_TOTAL>>>(edge_attr, ei, coords, We, eout);
    finalize_kernel<<<(NNODES * HD + 255) / 256, 256>>>(hout);
}

// round 10
// speedup vs baseline: 1.8611x; 1.8611x over previous
#include <cuda_runtime.h>
#include <cuda_bf16.h>
#include <math.h>
#include <stdint.h>

#define NNODES 16000
#define DIN    256
#define HD     256
#define NH     8
#define NEDGES 256000

// ---------------- device scratch ----------------
__device__ float g_q[NNODES * HD];
__device__ float g_k[NNODES * HD];
__device__ float g_v[NNODES * HD];
__device__ float g_wV[NNODES * HD];
__device__ float g_z[NNODES * NH];
// transposed bf16 weight images: [mat][n=256][k=256]; mat: 0=Wq 1=Wk 2=Wv 3=We
__device__ __nv_bfloat16 g_Bth[4][256 * 256];
__device__ __nv_bfloat16 g_Btl[4][256 * 256];

// ---------------- helpers ----------------
__device__ __forceinline__ void mma16816(float* d, const uint32_t* a, const uint32_t* b) {
    asm volatile(
        "mma.sync.aligned.m16n8k16.row.col.f32.bf16.bf16.f32 "
        "{%0,%1,%2,%3}, {%4,%5,%6,%7}, {%8,%9}, {%0,%1,%2,%3};"
        : "+f"(d[0]), "+f"(d[1]), "+f"(d[2]), "+f"(d[3])
        : "r"(a[0]), "r"(a[1]), "r"(a[2]), "r"(a[3]), "r"(b[0]), "r"(b[1]));
}
__device__ __forceinline__ uint32_t smem_u32(const void* p) {
    uint32_t a;
    asm("{ .reg .u64 t; cvta.to.shared.u64 t, %1; cvt.u32.u64 %0, t; }" : "=r"(a) : "l"(p));
    return a;
}
__device__ __forceinline__ void cp_async16(uint32_t dst, const void* src) {
    asm volatile("cp.async.cg.shared.global [%0], [%1], 16;" :: "r"(dst), "l"(src));
}
#define CP_COMMIT asm volatile("cp.async.commit_group;" ::: "memory")
#define CP_WAIT0  asm volatile("cp.async.wait_group 0;" ::: "memory")
#define LDSM4(r, addr) \
    asm volatile("ldmatrix.sync.aligned.m8n8.x4.shared.b16 {%0,%1,%2,%3}, [%4];" \
        : "=r"((r)[0]), "=r"((r)[1]), "=r"((r)[2]), "=r"((r)[3]) : "r"(addr))

// SMEM layout (bytes). A/B tiles use 80B rows (conflict-free ldsm).
// A: 128 rows x 32 k (hi 10240 + lo 10240) x 2 bufs
// B: 128 n   x 32 k (hi 10240 + lo 10240) x 2 bufs
// Alpha staging tile (epilogue, reuses A/B region): 128 x 136 floats = 69632 B
#define SM_SRC   0
#define SM_DST   512
#define SM_DIST  1024
#define SM_A     3584
#define ABUF     20480
#define SM_B     44544
#define BBUF     20480
#define SM_ALPHA 3584
#define ALPHA_STRIDE 136
#define SM_TOTAL 85504

// ---------------------------------------------------------------------------
__global__ void zero_kernel(const float* __restrict__ coords, float* __restrict__ cout) {
    int i = blockIdx.x * blockDim.x + threadIdx.x;
    if (i < NNODES * HD) g_wV[i] = 0.0f;
    if (i < NNODES * NH) g_z[i] = 0.0f;
    if (i < NNODES * 3)  cout[i] = coords[i];
}

// ---------------------------------------------------------------------------
// Weight prep: W[k][n] fp32 -> g_Bt{h,l}[mat][n][k] bf16 (hi/lo split).
// ---------------------------------------------------------------------------
__global__ void prep_weights(const float* __restrict__ Wq, const float* __restrict__ Wk,
                             const float* __restrict__ Wv, const float* __restrict__ We) {
    int t = blockIdx.x * blockDim.x + threadIdx.x;
    if (t >= 4 * 256 * 32) return;
    int mat = t >> 13;
    int rem = t & 8191;
    int n   = rem >> 5;
    int ku  = rem & 31;
    const float* W = mat == 0 ? Wq : mat == 1 ? Wk : mat == 2 ? Wv : We;
    uint32_t h[4], l[4];
    #pragma unroll
    for (int p = 0; p < 4; ++p) {
        float f0 = W[(ku * 8 + 2 * p) * HD + n];
        float f1 = W[(ku * 8 + 2 * p + 1) * HD + n];
        __nv_bfloat162 hh = __floats2bfloat162_rn(f0, f1);
        float l0 = f0 - __bfloat162float(hh.x);
        float l1 = f1 - __bfloat162float(hh.y);
        __nv_bfloat162 ll = __floats2bfloat162_rn(l0, l1);
        h[p] = *(uint32_t*)&hh;
        l[p] = *(uint32_t*)&ll;
    }
    *(uint4*)&g_Bth[mat][n * 256 + ku * 8] = make_uint4(h[0], h[1], h[2], h[3]);
    *(uint4*)&g_Btl[mat][n * 256 + ku * 8] = make_uint4(l[0], l[1], l[2], l[3]);
}

// ---------------------------------------------------------------------------
// A convert+store: 256 threads, each handles 16 k-floats of one row.
// ---------------------------------------------------------------------------
__device__ __forceinline__ void convert_store_A(char* smem, int buf, int tid,
                                                const float4* f) {
    int r = tid >> 1, u = tid & 1;
    const float* fv = (const float*)f;
    uint32_t h[8], l[8];
    #pragma unroll
    for (int p = 0; p < 8; ++p) {
        __nv_bfloat162 hh = __floats2bfloat162_rn(fv[2 * p], fv[2 * p + 1]);
        float l0 = fv[2 * p] - __bfloat162float(hh.x);
        float l1 = fv[2 * p + 1] - __bfloat162float(hh.y);
        __nv_bfloat162 ll = __floats2bfloat162_rn(l0, l1);
        h[p] = *(uint32_t*)&hh;
        l[p] = *(uint32_t*)&ll;
    }
    char* base = smem + SM_A + buf * ABUF + r * 80 + u * 32;
    *(uint4*)(base)              = make_uint4(h[0], h[1], h[2], h[3]);
    *(uint4*)(base + 16)         = make_uint4(h[4], h[5], h[6], h[7]);
    *(uint4*)(base + 10240)      = make_uint4(l[0], l[1], l[2], l[3]);
    *(uint4*)(base + 10240 + 16) = make_uint4(l[4], l[5], l[6], l[7]);
}

// ---------------------------------------------------------------------------
// GEMM mainloop: acc[2][8][4] += split-bf16( A[m0:128, :256] @ W[n0:128]^T )
// 256 threads, 8 warps (4 m x 2 n); warp tile 32 x 64. Double-buffered.
// ---------------------------------------------------------------------------
__device__ __forceinline__ void gemm_tile(char* smem, uint32_t sb,
                                          const float* __restrict__ A, int m0,
                                          int mat, int n0, int tid, float acc[2][8][4]) {
    int lane = tid & 31, w = tid >> 5;
    int warp_m = w & 3, warp_n = w >> 2;
    const __nv_bfloat16* Bh = g_Bth[mat] + (size_t)n0 * 256;
    const __nv_bfloat16* Bl = g_Btl[mat] + (size_t)n0 * 256;
    int r = tid >> 1, u = tid & 1;

    uint32_t aRow = (uint32_t)(warp_m * 32 + (lane & 7) + ((lane >> 3) & 1) * 8);
    uint32_t aOff = aRow * 80 + ((lane >> 4) & 1) * 16;
    uint32_t bRow = (uint32_t)(warp_n * 64 + (lane & 7) + ((lane >> 4) & 1) * 8);
    uint32_t bOff = bRow * 80 + ((lane >> 3) & 1) * 16;

    // prologue: chunk 0
    {
        float4 f[4];
        const float4* src = (const float4*)(A + (size_t)(m0 + r) * DIN + u * 16);
        f[0] = src[0]; f[1] = src[1]; f[2] = src[2]; f[3] = src[3];
        #pragma unroll
        for (int i = 0; i < 2; ++i) {
            int un = tid + 256 * i;            // 0..511
            int n = un >> 2, uu = un & 3;
            cp_async16(sb + SM_B + n * 80 + uu * 16,         &Bh[n * 256 + uu * 8]);
            cp_async16(sb + SM_B + 10240 + n * 80 + uu * 16, &Bl[n * 256 + uu * 8]);
        }
        CP_COMMIT;
        convert_store_A(smem, 0, tid, f);
        CP_WAIT0;
        __syncthreads();
    }

    for (int kc = 0; kc < 8; ++kc) {
        int cur = kc & 1, nxt = cur ^ 1;
        float4 f[4];
        if (kc < 7) {
            const float4* src = (const float4*)(A + (size_t)(m0 + r) * DIN + (kc + 1) * 32 + u * 16);
            f[0] = src[0]; f[1] = src[1]; f[2] = src[2]; f[3] = src[3];
            #pragma unroll
            for (int i = 0; i < 2; ++i) {
                int un = tid + 256 * i;
                int n = un >> 2, uu = un & 3;
                cp_async16(sb + SM_B + nxt * BBUF + n * 80 + uu * 16,
                           &Bh[n * 256 + (kc + 1) * 32 + uu * 8]);
                cp_async16(sb + SM_B + nxt * BBUF + 10240 + n * 80 + uu * 16,
                           &Bl[n * 256 + (kc + 1) * 32 + uu * 8]);
            }
            CP_COMMIT;
        }

        uint32_t aBase = sb + SM_A + cur * ABUF + aOff;
        uint32_t bBase = sb + SM_B + cur * BBUF + bOff;
        #pragma unroll
        for (int ks = 0; ks < 2; ++ks) {
            uint32_t ah[2][4], al[2][4];
            LDSM4(ah[0], aBase + ks * 32);
            LDSM4(ah[1], aBase + ks * 32 + 1280);            // +16 rows
            LDSM4(al[0], aBase + ks * 32 + 10240);
            LDSM4(al[1], aBase + ks * 32 + 10240 + 1280);
            uint32_t bh[4][4], bl[4][4];
            #pragma unroll
            for (int pr = 0; pr < 4; ++pr) {
                LDSM4(bh[pr], bBase + ks * 32 + pr * 1280);
                LDSM4(bl[pr], bBase + ks * 32 + pr * 1280 + 10240);
            }
            #pragma unroll
            for (int pr = 0; pr < 4; ++pr) {
                #pragma unroll
                for (int sub = 0; sub < 2; ++sub) {
                    int nf = pr * 2 + sub;
                    uint32_t b2h[2] = {bh[pr][2 * sub], bh[pr][2 * sub + 1]};
                    uint32_t b2l[2] = {bl[pr][2 * sub], bl[pr][2 * sub + 1]};
                    #pragma unroll
                    for (int mf = 0; mf < 2; ++mf) {
                        mma16816(acc[mf][nf], ah[mf], b2h);
                        mma16816(acc[mf][nf], al[mf], b2h);
                        mma16816(acc[mf][nf], ah[mf], b2l);
                    }
                }
            }
        }

        if (kc < 7) {
            convert_store_A(smem, nxt, tid, f);
            CP_WAIT0;
            __syncthreads();
        }
    }
}

// ---------------------------------------------------------------------------
// QKV GEMM. grid (125, 3, 2), 256 threads.
// ---------------------------------------------------------------------------
__global__ __launch_bounds__(256, 2) void qkv_mm(const float* __restrict__ x) {
    extern __shared__ char smem[];
    uint32_t sb = smem_u32(smem);
    int tid = threadIdx.x;
    int m0 = blockIdx.x * 128;
    int mat = blockIdx.y;
    int n0 = blockIdx.z * 128;

    float acc[2][8][4];
    #pragma unroll
    for (int mf = 0; mf < 2; ++mf)
        #pragma unroll
        for (int nf = 0; nf < 8; ++nf)
            #pragma unroll
            for (int p = 0; p < 4; ++p) acc[mf][nf][p] = 0.0f;

    gemm_tile(smem, sb, x, m0, mat, n0, tid, acc);

    int lane = tid & 31, w = tid >> 5;
    int warp_m = w & 3, warp_n = w >> 2;
    int qrow = lane >> 2, qcol = lane & 3;
    float* out = mat == 0 ? g_q : mat == 1 ? g_k : g_v;

    #pragma unroll
    for (int mf = 0; mf < 2; ++mf) {
        int r0 = m0 + warp_m * 32 + mf * 16 + qrow;
        #pragma unroll
        for (int nf = 0; nf < 8; ++nf) {
            int c = n0 + warp_n * 64 + nf * 8 + qcol * 2;
            *(float2*)(out + (size_t)r0 * HD + c)       = make_float2(acc[mf][nf][0], acc[mf][nf][1]);
            *(float2*)(out + (size_t)(r0 + 8) * HD + c) = make_float2(acc[mf][nf][2], acc[mf][nf][3]);
        }
    }
}

// ---------------------------------------------------------------------------
// Edge GEMM + transposed fused epilogue. grid (2000, 2), 256 threads.
// Each CTA: 128 edges x 128 cols (4 heads).
// Epilogue: stage acc to smem, then warp-per-16-edges with lanes spanning
// 128 consecutive cols -> fully coalesced float4 k/q/v/e_out/wV accesses.
// ---------------------------------------------------------------------------
__global__ __launch_bounds__(256, 2) void edge_mm(const float* __restrict__ edge_attr,
                                                  const int* __restrict__ ei,
                                                  const float* __restrict__ coords,
                                                  const float* __restrict__ We,
                                                  float* __restrict__ eout) {
    extern __shared__ char smem[];
    uint32_t sb = smem_u32(smem);
    int tid = threadIdx.x;
    int m0 = blockIdx.x * 128;
    int n0 = blockIdx.y * 128;
    int hbase = n0 >> 5;                        // first head of this CTA (4 heads)

    int*   sSrc = (int*)(smem + SM_SRC);
    int*   sDst = (int*)(smem + SM_DST);
    float* sDist = (float*)(smem + SM_DIST);

    if (tid < 128) {
        int s = ei[m0 + tid];
        int d = ei[NEDGES + m0 + tid];
        sSrc[tid] = s; sDst[tid] = d;
        float dx = coords[3 * s + 0] - coords[3 * d + 0];
        float dy = coords[3 * s + 1] - coords[3 * d + 1];
        float dz = coords[3 * s + 2] - coords[3 * d + 2];
        sDist[tid] = 0.1f * sqrtf(dx * dx + dy * dy + dz * dz);
    }
    __syncthreads();

    float acc[2][8][4];
    #pragma unroll
    for (int mf = 0; mf < 2; ++mf)
        #pragma unroll
        for (int nf = 0; nf < 8; ++nf)
            #pragma unroll
            for (int p = 0; p < 4; ++p) acc[mf][nf][p] = 0.0f;

    gemm_tile(smem, sb, edge_attr, m0, 3, n0, tid, acc);

    int lane = tid & 31, w = tid >> 5;
    int warp_m = w & 3, warp_n = w >> 2;
    int qrow = lane >> 2, qcol = lane & 3;

    // ---- stage raw acc into smem alpha tile [128][136] (reuses A/B bufs) ----
    __syncthreads();   // all warps done reading mainloop smem
    float* alpha = (float*)(smem + SM_ALPHA);
    #pragma unroll
    for (int mf = 0; mf < 2; ++mf) {
        int r0 = warp_m * 32 + mf * 16 + qrow;
        #pragma unroll
        for (int nf = 0; nf < 8; ++nf) {
            int c = warp_n * 64 + nf * 8 + qcol * 2;
            *(float2*)&alpha[r0 * ALPHA_STRIDE + c]       = make_float2(acc[mf][nf][0], acc[mf][nf][1]);
            *(float2*)&alpha[(r0 + 8) * ALPHA_STRIDE + c] = make_float2(acc[mf][nf][2], acc[mf][nf][3]);
        }
    }
    __syncthreads();

    // ---- transposed epilogue: warp w handles edges w*16 .. w*16+15 ----
    const float invs = 0.17677669529663687f;   // 1/sqrt(32)
    int gc = n0 + lane * 4;                    // global col (lane's 4 cols, one head per 8 lanes)
    int hloc = lane >> 3;                      // local head 0..3
    float4 wl4 = *(const float4*)(We + (size_t)DIN * HD + gc);

    #pragma unroll 2
    for (int i = 0; i < 16; ++i) {
        int e = w * 16 + i;
        int src = sSrc[e], dst = sDst[e];
        float de = sDist[e];
        float4 d4 = *(const float4*)&alpha[e * ALPHA_STRIDE + lane * 4];
        float4 k4 = *(const float4*)(g_k + (size_t)src * HD + gc);
        float4 q4 = *(const float4*)(g_q + (size_t)dst * HD + gc);
        float4 a4;
        float s;
        s = fminf(5.0f, fmaxf(-5.0f, k4.x * q4.x * invs)); a4.x = s * (d4.x + de * wl4.x);
        s = fminf(5.0f, fmaxf(-5.0f, k4.y * q4.y * invs)); a4.y = s * (d4.y + de * wl4.y);
        s = fminf(5.0f, fmaxf(-5.0f, k4.z * q4.z * invs)); a4.z = s * (d4.z + de * wl4.z);
        s = fminf(5.0f, fmaxf(-5.0f, k4.w * q4.w * invs)); a4.w = s * (d4.w + de * wl4.w);
        *(float4*)(eout + (size_t)(m0 + e) * HD + gc) = a4;

        // head sum over the 8-lane group (32 cols = 1 head)
        float part = (a4.x + a4.y) + (a4.z + a4.w);
        part += __shfl_xor_sync(0xffffffffu, part, 1);
        part += __shfl_xor_sync(0xffffffffu, part, 2);
        part += __shfl_xor_sync(0xffffffffu, part, 4);
        float ax = expf(fminf(5.0f, fmaxf(-5.0f, part)));

        // scatter: wV[dst] += v[src] * ax (coalesced float4 per group)
        float4 v4 = *(const float4*)(g_v + (size_t)src * HD + gc);
        float* wv = g_wV + (size_t)dst * HD + gc;
        atomicAdd(wv + 0, v4.x * ax);
        atomicAdd(wv + 1, v4.y * ax);
        atomicAdd(wv + 2, v4.z * ax);
        atomicAdd(wv + 3, v4.w * ax);
        if ((lane & 7) == 0)
            atomicAdd(&g_z[(size_t)dst * NH + hbase + hloc], ax);
    }
}

// ---------------------------------------------------------------------------
__global__ void finalize_kernel(float* __restrict__ hout) {
    int i = blockIdx.x * blockDim.x + threadIdx.x;
    if (i < NNODES * HD) {
        int n = i >> 8;
        int h = (i & 255) >> 5;
        hout[i] = g_wV[i] / (g_z[n * NH + h] + 1e-6f);
    }
}

// ---------------------------------------------------------------------------
extern "C" void kernel_launch(void* const* d_in, const int* in_sizes, int n_in,
                              void* d_out, int out_size)
{
    const float* x         = (const float*)d_in[0];
    const float* edge_attr = (const float*)d_in[1];
    const int*   ei        = (const int*)d_in[2];
    const float* coords    = (const float*)d_in[3];
    const float* Wq        = (const float*)d_in[4];
    const float* Wk        = (const float*)d_in[5];
    const float* Wv        = (const float*)d_in[6];
    const float* We        = (const float*)d_in[7];

    float* out  = (float*)d_out;
    float* hout = out;
    float* eout = out + (size_t)NNODES * HD;
    float* cout = eout + (size_t)NEDGES * HD;

    static bool attr_set = false;
    if (!attr_set) {
        cudaFuncSetAttribute(qkv_mm,  cudaFuncAttributeMaxDynamicSharedMemorySize, SM_TOTAL);
        cudaFuncSetAttribute(edge_mm, cudaFuncAttributeMaxDynamicSharedMemorySize, SM_TOTAL);
        attr_set = true;
    }

    zero_kernel<<<(NNODES * HD + 255) / 256, 256>>>(coords, cout);
    prep_weights<<<128, 256>>>(Wq, Wk, Wv, We);
    qkv_mm<<<dim3(125, 3, 2), 256, SM_TOTAL>>>(x);
    edge_mm<<<dim3(2000, 2), 256, SM_TOTAL>>>(edge_attr, ei, coords, We, eout);
    finalize_kernel<<<(NNODES * HD + 255) / 256, 256>>>(hout);
}

// round 11
// speedup vs baseline: 1.9670x; 1.0569x over previous
#include <cuda_runtime.h>
#include <cuda_bf16.h>
#include <math.h>
#include <stdint.h>

#define NNODES 16000
#define DIN    256
#define HD     256
#define NH     8
#define NEDGES 256000

// ---------------- device scratch ----------------
__device__ float g_q[NNODES * HD];
__device__ float g_k[NNODES * HD];
__device__ float g_v[NNODES * HD];
__device__ float g_wV[NNODES * HD];
__device__ float g_z[NNODES * NH];
// transposed bf16 weight images: [mat][n=256][k=256]; mat: 0=Wq 1=Wk 2=Wv 3=We
__device__ __nv_bfloat16 g_Bth[4][256 * 256];
__device__ __nv_bfloat16 g_Btl[4][256 * 256];

// ---------------- helpers ----------------
__device__ __forceinline__ void mma16816(float* d, const uint32_t* a, const uint32_t* b) {
    asm volatile(
        "mma.sync.aligned.m16n8k16.row.col.f32.bf16.bf16.f32 "
        "{%0,%1,%2,%3}, {%4,%5,%6,%7}, {%8,%9}, {%0,%1,%2,%3};"
        : "+f"(d[0]), "+f"(d[1]), "+f"(d[2]), "+f"(d[3])
        : "r"(a[0]), "r"(a[1]), "r"(a[2]), "r"(a[3]), "r"(b[0]), "r"(b[1]));
}
__device__ __forceinline__ uint32_t smem_u32(const void* p) {
    uint32_t a;
    asm("{ .reg .u64 t; cvta.to.shared.u64 t, %1; cvt.u32.u64 %0, t; }" : "=r"(a) : "l"(p));
    return a;
}
__device__ __forceinline__ void cp_async16(uint32_t dst, const void* src) {
    asm volatile("cp.async.cg.shared.global [%0], [%1], 16;" :: "r"(dst), "l"(src));
}
#define CP_COMMIT asm volatile("cp.async.commit_group;" ::: "memory")
#define CP_WAIT0  asm volatile("cp.async.wait_group 0;" ::: "memory")
#define LDSM4(r, addr) \
    asm volatile("ldmatrix.sync.aligned.m8n8.x4.shared.b16 {%0,%1,%2,%3}, [%4];" \
        : "=r"((r)[0]), "=r"((r)[1]), "=r"((r)[2]), "=r"((r)[3]) : "r"(addr))

// SMEM layout (bytes). A/B tiles use 80B rows (conflict-free ldsm).
// A: 64 rows x 32 k (hi 5120 + lo 5120) x 2 bufs   = 20480
// B: 256 n  x 32 k (hi 20480 + lo 20480) x 2 bufs  = 81920
// Alpha staging (epilogue, reuses A/B region): 64 x 264 floats = 67584 B
#define SM_SRC   0
#define SM_DST   256
#define SM_DIST  512
#define SM_A     1024
#define ABUF     10240
#define SM_B     21504
#define BBUF     40960
#define SM_ALPHA 1024
#define ALPHA_STRIDE 264
#define SM_TOTAL 103424

// ---------------------------------------------------------------------------
__global__ void zero_kernel(const float* __restrict__ coords, float* __restrict__ cout) {
    int i = blockIdx.x * blockDim.x + threadIdx.x;
    if (i < NNODES * HD) g_wV[i] = 0.0f;
    if (i < NNODES * NH) g_z[i] = 0.0f;
    if (i < NNODES * 3)  cout[i] = coords[i];
}

// ---------------------------------------------------------------------------
// Weight prep: W[k][n] fp32 -> g_Bt{h,l}[mat][n][k] bf16 (hi/lo split).
// ---------------------------------------------------------------------------
__global__ void prep_weights(const float* __restrict__ Wq, const float* __restrict__ Wk,
                             const float* __restrict__ Wv, const float* __restrict__ We) {
    int t = blockIdx.x * blockDim.x + threadIdx.x;
    if (t >= 4 * 256 * 32) return;
    int mat = t >> 13;
    int rem = t & 8191;
    int n   = rem >> 5;
    int ku  = rem & 31;
    const float* W = mat == 0 ? Wq : mat == 1 ? Wk : mat == 2 ? Wv : We;
    uint32_t h[4], l[4];
    #pragma unroll
    for (int p = 0; p < 4; ++p) {
        float f0 = W[(ku * 8 + 2 * p) * HD + n];
        float f1 = W[(ku * 8 + 2 * p + 1) * HD + n];
        __nv_bfloat162 hh = __floats2bfloat162_rn(f0, f1);
        float l0 = f0 - __bfloat162float(hh.x);
        float l1 = f1 - __bfloat162float(hh.y);
        __nv_bfloat162 ll = __floats2bfloat162_rn(l0, l1);
        h[p] = *(uint32_t*)&hh;
        l[p] = *(uint32_t*)&ll;
    }
    *(uint4*)&g_Bth[mat][n * 256 + ku * 8] = make_uint4(h[0], h[1], h[2], h[3]);
    *(uint4*)&g_Btl[mat][n * 256 + ku * 8] = make_uint4(l[0], l[1], l[2], l[3]);
}

// ---------------------------------------------------------------------------
// A convert+store: 256 threads, each 8 k-floats of one row (64 rows x 32 k).
// ---------------------------------------------------------------------------
__device__ __forceinline__ void convert_store_A(char* smem, int buf, int tid,
                                                float4 f0, float4 f1) {
    int r = tid >> 2, u = tid & 3;
    float fv[8] = {f0.x, f0.y, f0.z, f0.w, f1.x, f1.y, f1.z, f1.w};
    uint32_t h[4], l[4];
    #pragma unroll
    for (int p = 0; p < 4; ++p) {
        __nv_bfloat162 hh = __floats2bfloat162_rn(fv[2 * p], fv[2 * p + 1]);
        float l0 = fv[2 * p] - __bfloat162float(hh.x);
        float l1 = fv[2 * p + 1] - __bfloat162float(hh.y);
        __nv_bfloat162 ll = __floats2bfloat162_rn(l0, l1);
        h[p] = *(uint32_t*)&hh;
        l[p] = *(uint32_t*)&ll;
    }
    char* base = smem + SM_A + buf * ABUF + r * 80 + u * 16;
    *(uint4*)(base)        = make_uint4(h[0], h[1], h[2], h[3]);
    *(uint4*)(base + 5120) = make_uint4(l[0], l[1], l[2], l[3]);
}

// ---------------------------------------------------------------------------
// GEMM mainloop: acc[2][8][4] += split-bf16( A[m0:64, :256] @ W[0:256]^T )
// 256 threads, 8 warps (2 m x 4 n); warp tile 32 x 64. Double-buffered.
// ---------------------------------------------------------------------------
__device__ __forceinline__ void gemm_tile(char* smem, uint32_t sb,
                                          const float* __restrict__ A, int m0,
                                          int mat, int tid, float acc[2][8][4]) {
    int lane = tid & 31, w = tid >> 5;
    int warp_m = w & 1, warp_n = w >> 1;
    const __nv_bfloat16* Bh = g_Bth[mat];
    const __nv_bfloat16* Bl = g_Btl[mat];
    int r = tid >> 2, u = tid & 3;

    uint32_t aRow = (uint32_t)(warp_m * 32 + (lane & 7) + ((lane >> 3) & 1) * 8);
    uint32_t aOff = aRow * 80 + ((lane >> 4) & 1) * 16;
    uint32_t bRow = (uint32_t)(warp_n * 64 + (lane & 7) + ((lane >> 4) & 1) * 8);
    uint32_t bOff = bRow * 80 + ((lane >> 3) & 1) * 16;

    // prologue: chunk 0
    {
        const float4* src = (const float4*)(A + (size_t)(m0 + r) * DIN + u * 8);
        float4 f0 = src[0], f1 = src[1];
        #pragma unroll
        for (int i = 0; i < 4; ++i) {
            int un = tid + 256 * i;            // 0..1023
            int n = un >> 2, uu = un & 3;
            cp_async16(sb + SM_B + n * 80 + uu * 16,         &Bh[n * 256 + uu * 8]);
            cp_async16(sb + SM_B + 20480 + n * 80 + uu * 16, &Bl[n * 256 + uu * 8]);
        }
        CP_COMMIT;
        convert_store_A(smem, 0, tid, f0, f1);
        CP_WAIT0;
        __syncthreads();
    }

    for (int kc = 0; kc < 8; ++kc) {
        int cur = kc & 1, nxt = cur ^ 1;
        float4 f0, f1;
        if (kc < 7) {
            const float4* src = (const float4*)(A + (size_t)(m0 + r) * DIN + (kc + 1) * 32 + u * 8);
            f0 = src[0]; f1 = src[1];
            #pragma unroll
            for (int i = 0; i < 4; ++i) {
                int un = tid + 256 * i;
                int n = un >> 2, uu = un & 3;
                cp_async16(sb + SM_B + nxt * BBUF + n * 80 + uu * 16,
                           &Bh[n * 256 + (kc + 1) * 32 + uu * 8]);
                cp_async16(sb + SM_B + nxt * BBUF + 20480 + n * 80 + uu * 16,
                           &Bl[n * 256 + (kc + 1) * 32 + uu * 8]);
            }
            CP_COMMIT;
        }

        uint32_t aBase = sb + SM_A + cur * ABUF + aOff;
        uint32_t bBase = sb + SM_B + cur * BBUF + bOff;
        #pragma unroll
        for (int ks = 0; ks < 2; ++ks) {
            uint32_t ah[2][4], al[2][4];
            LDSM4(ah[0], aBase + ks * 32);
            LDSM4(ah[1], aBase + ks * 32 + 1280);            // +16 rows
            LDSM4(al[0], aBase + ks * 32 + 5120);
            LDSM4(al[1], aBase + ks * 32 + 5120 + 1280);
            uint32_t bh[4][4], bl[4][4];
            #pragma unroll
            for (int pr = 0; pr < 4; ++pr) {
                LDSM4(bh[pr], bBase + ks * 32 + pr * 1280);
                LDSM4(bl[pr], bBase + ks * 32 + pr * 1280 + 20480);
            }
            #pragma unroll
            for (int pr = 0; pr < 4; ++pr) {
                #pragma unroll
                for (int sub = 0; sub < 2; ++sub) {
                    int nf = pr * 2 + sub;
                    uint32_t b2h[2] = {bh[pr][2 * sub], bh[pr][2 * sub + 1]};
                    uint32_t b2l[2] = {bl[pr][2 * sub], bl[pr][2 * sub + 1]};
                    #pragma unroll
                    for (int mf = 0; mf < 2; ++mf) {
                        mma16816(acc[mf][nf], ah[mf], b2h);
                        mma16816(acc[mf][nf], al[mf], b2h);
                        mma16816(acc[mf][nf], ah[mf], b2l);
                    }
                }
            }
        }

        if (kc < 7) {
            convert_store_A(smem, nxt, tid, f0, f1);
            CP_WAIT0;
            __syncthreads();
        }
    }
}

// ---------------------------------------------------------------------------
// QKV GEMM. grid (250, 3), 256 threads. CTA tile 64 x 256.
// ---------------------------------------------------------------------------
__global__ __launch_bounds__(256, 2) void qkv_mm(const float* __restrict__ x) {
    extern __shared__ char smem[];
    uint32_t sb = smem_u32(smem);
    int tid = threadIdx.x;
    int m0 = blockIdx.x * 64;
    int mat = blockIdx.y;

    float acc[2][8][4];
    #pragma unroll
    for (int mf = 0; mf < 2; ++mf)
        #pragma unroll
        for (int nf = 0; nf < 8; ++nf)
            #pragma unroll
            for (int p = 0; p < 4; ++p) acc[mf][nf][p] = 0.0f;

    gemm_tile(smem, sb, x, m0, mat, tid, acc);

    int lane = tid & 31, w = tid >> 5;
    int warp_m = w & 1, warp_n = w >> 1;
    int qrow = lane >> 2, qcol = lane & 3;
    float* out = mat == 0 ? g_q : mat == 1 ? g_k : g_v;

    #pragma unroll
    for (int mf = 0; mf < 2; ++mf) {
        int r0 = m0 + warp_m * 32 + mf * 16 + qrow;
        #pragma unroll
        for (int nf = 0; nf < 8; ++nf) {
            int c = warp_n * 64 + nf * 8 + qcol * 2;
            *(float2*)(out + (size_t)r0 * HD + c)       = make_float2(acc[mf][nf][0], acc[mf][nf][1]);
            *(float2*)(out + (size_t)(r0 + 8) * HD + c) = make_float2(acc[mf][nf][2], acc[mf][nf][3]);
        }
    }
}

// ---------------------------------------------------------------------------
// Edge GEMM + transposed fused epilogue. grid 4000, 256 threads.
// Each CTA: 64 edges x 256 cols (all 8 heads).
// ---------------------------------------------------------------------------
__global__ __launch_bounds__(256, 2) void edge_mm(const float* __restrict__ edge_attr,
                                                  const int* __restrict__ ei,
                                                  const float* __restrict__ coords,
                                                  const float* __restrict__ We,
                                                  float* __restrict__ eout) {
    extern __shared__ char smem[];
    uint32_t sb = smem_u32(smem);
    int tid = threadIdx.x;
    int m0 = blockIdx.x * 64;

    int*   sSrc = (int*)(smem + SM_SRC);
    int*   sDst = (int*)(smem + SM_DST);
    float* sDist = (float*)(smem + SM_DIST);

    if (tid < 64) {
        int s = ei[m0 + tid];
        int d = ei[NEDGES + m0 + tid];
        sSrc[tid] = s; sDst[tid] = d;
        float dx = coords[3 * s + 0] - coords[3 * d + 0];
        float dy = coords[3 * s + 1] - coords[3 * d + 1];
        float dz = coords[3 * s + 2] - coords[3 * d + 2];
        sDist[tid] = 0.1f * sqrtf(dx * dx + dy * dy + dz * dz);
    }
    __syncthreads();

    float acc[2][8][4];
    #pragma unroll
    for (int mf = 0; mf < 2; ++mf)
        #pragma unroll
        for (int nf = 0; nf < 8; ++nf)
            #pragma unroll
            for (int p = 0; p < 4; ++p) acc[mf][nf][p] = 0.0f;

    gemm_tile(smem, sb, edge_attr, m0, 3, tid, acc);

    int lane = tid & 31, w = tid >> 5;
    int warp_m = w & 1, warp_n = w >> 1;
    int qrow = lane >> 2, qcol = lane & 3;

    // ---- stage raw acc into smem alpha tile [64][264] (reuses A/B bufs) ----
    __syncthreads();
    float* alpha = (float*)(smem + SM_ALPHA);
    #pragma unroll
    for (int mf = 0; mf < 2; ++mf) {
        int r0 = warp_m * 32 + mf * 16 + qrow;
        #pragma unroll
        for (int nf = 0; nf < 8; ++nf) {
            int c = warp_n * 64 + nf * 8 + qcol * 2;
            *(float2*)&alpha[r0 * ALPHA_STRIDE + c]       = make_float2(acc[mf][nf][0], acc[mf][nf][1]);
            *(float2*)&alpha[(r0 + 8) * ALPHA_STRIDE + c] = make_float2(acc[mf][nf][2], acc[mf][nf][3]);
        }
    }
    __syncthreads();

    // ---- transposed epilogue: warp w handles edges w*8 .. w*8+7 ----
    const float invs = 0.17677669529663687f;   // 1/sqrt(32)
    int c0 = lane * 4;                          // first-half col
    int c1 = 128 + lane * 4;                    // second-half col
    int h0 = lane >> 3;                         // head of c0 group (0..3)
    float4 wlA = *(const float4*)(We + (size_t)DIN * HD + c0);
    float4 wlB = *(const float4*)(We + (size_t)DIN * HD + c1);

    #pragma unroll 2
    for (int i = 0; i < 8; ++i) {
        int e = w * 8 + i;
        int src = sSrc[e], dst = sDst[e];
        float de = sDist[e];
        const float* krow = g_k + (size_t)src * HD;
        const float* qrow_p = g_q + (size_t)dst * HD;
        float4 dA = *(const float4*)&alpha[e * ALPHA_STRIDE + c0];
        float4 dB = *(const float4*)&alpha[e * ALPHA_STRIDE + c1];
        float4 kA = *(const float4*)(krow + c0);
        float4 kB = *(const float4*)(krow + c1);
        float4 qA = *(const float4*)(qrow_p + c0);
        float4 qB = *(const float4*)(qrow_p + c1);
        float4 aA, aB;
        float s;
        s = fminf(5.0f, fmaxf(-5.0f, kA.x * qA.x * invs)); aA.x = s * (dA.x + de * wlA.x);
        s = fminf(5.0f, fmaxf(-5.0f, kA.y * qA.y * invs)); aA.y = s * (dA.y + de * wlA.y);
        s = fminf(5.0f, fmaxf(-5.0f, kA.z * qA.z * invs)); aA.z = s * (dA.z + de * wlA.z);
        s = fminf(5.0f, fmaxf(-5.0f, kA.w * qA.w * invs)); aA.w = s * (dA.w + de * wlA.w);
        s = fminf(5.0f, fmaxf(-5.0f, kB.x * qB.x * invs)); aB.x = s * (dB.x + de * wlB.x);
        s = fminf(5.0f, fmaxf(-5.0f, kB.y * qB.y * invs)); aB.y = s * (dB.y + de * wlB.y);
        s = fminf(5.0f, fmaxf(-5.0f, kB.z * qB.z * invs)); aB.z = s * (dB.z + de * wlB.z);
        s = fminf(5.0f, fmaxf(-5.0f, kB.w * qB.w * invs)); aB.w = s * (dB.w + de * wlB.w);
        float* eo = eout + (size_t)(m0 + e) * HD;
        *(float4*)(eo + c0) = aA;
        *(float4*)(eo + c1) = aB;

        // per-head sums over 8-lane groups (32 cols = 1 head)
        float pA = (aA.x + aA.y) + (aA.z + aA.w);
        float pB = (aB.x + aB.y) + (aB.z + aB.w);
        pA += __shfl_xor_sync(0xffffffffu, pA, 1);
        pB += __shfl_xor_sync(0xffffffffu, pB, 1);
        pA += __shfl_xor_sync(0xffffffffu, pA, 2);
        pB += __shfl_xor_sync(0xffffffffu, pB, 2);
        pA += __shfl_xor_sync(0xffffffffu, pA, 4);
        pB += __shfl_xor_sync(0xffffffffu, pB, 4);
        float axA = expf(fminf(5.0f, fmaxf(-5.0f, pA)));
        float axB = expf(fminf(5.0f, fmaxf(-5.0f, pB)));

        const float* vrow = g_v + (size_t)src * HD;
        float4 vA = *(const float4*)(vrow + c0);
        float4 vB = *(const float4*)(vrow + c1);
        float* wv = g_wV + (size_t)dst * HD;
        atomicAdd(wv + c0 + 0, vA.x * axA);
        atomicAdd(wv + c0 + 1, vA.y * axA);
        atomicAdd(wv + c0 + 2, vA.z * axA);
        atomicAdd(wv + c0 + 3, vA.w * axA);
        atomicAdd(wv + c1 + 0, vB.x * axB);
        atomicAdd(wv + c1 + 1, vB.y * axB);
        atomicAdd(wv + c1 + 2, vB.z * axB);
        atomicAdd(wv + c1 + 3, vB.w * axB);
        if ((lane & 7) == 0) {
            atomicAdd(&g_z[(size_t)dst * NH + h0], axA);
            atomicAdd(&g_z[(size_t)dst * NH + 4 + h0], axB);
        }
    }
}

// ---------------------------------------------------------------------------
__global__ void finalize_kernel(float* __restrict__ hout) {
    int i = blockIdx.x * blockDim.x + threadIdx.x;
    if (i < NNODES * HD) {
        int n = i >> 8;
        int h = (i & 255) >> 5;
        hout[i] = g_wV[i] / (g_z[n * NH + h] + 1e-6f);
    }
}

// ---------------------------------------------------------------------------
extern "C" void kernel_launch(void* const* d_in, const int* in_sizes, int n_in,
                              void* d_out, int out_size)
{
    const float* x         = (const float*)d_in[0];
    const float* edge_attr = (const float*)d_in[1];
    const int*   ei        = (const int*)d_in[2];
    const float* coords    = (const float*)d_in[3];
    const float* Wq        = (const float*)d_in[4];
    const float* Wk        = (const float*)d_in[5];
    const float* Wv        = (const float*)d_in[6];
    const float* We        = (const float*)d_in[7];

    float* out  = (float*)d_out;
    float* hout = out;
    float* eout = out + (size_t)NNODES * HD;
    float* cout = eout + (size_t)NEDGES * HD;

    static bool attr_set = false;
    if (!attr_set) {
        cudaFuncSetAttribute(qkv_mm,  cudaFuncAttributeMaxDynamicSharedMemorySize, SM_TOTAL);
        cudaFuncSetAttribute(edge_mm, cudaFuncAttributeMaxDynamicSharedMemorySize, SM_TOTAL);
        attr_set = true;
    }

    zero_kernel<<<(NNODES * HD + 255) / 256, 256>>>(coords, cout);
    prep_weights<<<128, 256>>>(Wq, Wk, Wv, We);
    qkv_mm<<<dim3(250, 3), 256, SM_TOTAL>>>(x);
    edge_mm<<<4000, 256, SM_TOTAL>>>(edge_attr, ei, coords, We, eout);
    finalize_kernel<<<(NNODES * HD + 255) / 256, 256>>>(hout);
}

// round 12
// speedup vs baseline: 2.4294x; 1.2351x over previous
#include <cuda_runtime.h>
#include <cuda_bf16.h>
#include <math.h>
#include <stdint.h>

#define NNODES 16000
#define DIN    256
#define HD     256
#define NH     8
#define NEDGES 256000

// ---------------- device scratch ----------------
__device__ float g_q[NNODES * HD];
__device__ float g_k[NNODES * HD];
__device__ float g_v[NNODES * HD];
__device__ float g_wV[NNODES * HD];
__device__ float g_z[NNODES * NH];
// tf32 weight images in mma-fragment order:
// [mat][ks 0..31][nb 0..31][lane 0..31][2]  (b0,b1) ; mat: 0=Wq 1=Wk 2=Wv 3=We
__device__ uint32_t g_Btf[4][32 * 32 * 32 * 2];

// ---------------- helpers ----------------
__device__ __forceinline__ uint32_t f2tf32(float f) {
    uint32_t r;
    asm("cvt.rna.tf32.f32 %0, %1;" : "=r"(r) : "f"(f));
    return r;
}
__device__ __forceinline__ void mma_tf32(float* d, const uint32_t* a, const uint32_t* b) {
    asm volatile(
        "mma.sync.aligned.m16n8k8.row.col.f32.tf32.tf32.f32 "
        "{%0,%1,%2,%3}, {%4,%5,%6,%7}, {%8,%9}, {%0,%1,%2,%3};"
        : "+f"(d[0]), "+f"(d[1]), "+f"(d[2]), "+f"(d[3])
        : "r"(a[0]), "r"(a[1]), "r"(a[2]), "r"(a[3]), "r"(b[0]), "r"(b[1]));
}
__device__ __forceinline__ uint32_t smem_u32(const void* p) {
    uint32_t a;
    asm("{ .reg .u64 t; cvta.to.shared.u64 t, %1; cvt.u32.u64 %0, t; }" : "=r"(a) : "l"(p));
    return a;
}
__device__ __forceinline__ void cp_async16(uint32_t dst, const void* src) {
    asm volatile("cp.async.cg.shared.global [%0], [%1], 16;" :: "r"(dst), "l"(src));
}
#define CP_COMMIT asm volatile("cp.async.commit_group;" ::: "memory")
#define CP_WAIT0  asm volatile("cp.async.wait_group 0;" ::: "memory")

// SMEM layout (bytes).
// A: 64 rows x 32 k fp32(tf32), stride 144B -> 9216 per buf, x2
// B: fragment-ordered chunk 32768 per buf, x2
// Alpha staging (epilogue, reuses A/B region): 64 x 264 floats = 67584
#define SM_SRC   0
#define SM_DST   256
#define SM_DIST  512
#define SM_A     1024
#define ABUF     9216
#define A_STRIDE 144
#define SM_B     19456
#define BBUF     32768
#define SM_ALPHA 1024
#define ALPHA_STRIDE 264
#define SM_TOTAL 84992

// ---------------------------------------------------------------------------
__global__ void zero_kernel(const float* __restrict__ coords, float* __restrict__ cout) {
    int i = blockIdx.x * blockDim.x + threadIdx.x;
    if (i < NNODES * HD) g_wV[i] = 0.0f;
    if (i < NNODES * NH) g_z[i] = 0.0f;
    if (i < NNODES * 3)  cout[i] = coords[i];
}

// ---------------------------------------------------------------------------
// Weight prep: W[k][n] fp32 -> tf32 fragment-ordered image.
// b0 = W[ks*8 + t%4][nb*8 + t/4], b1 = W[ks*8 + t%4 + 4][nb*8 + t/4]
// ---------------------------------------------------------------------------
__global__ void prep_weights(const float* __restrict__ Wq, const float* __restrict__ Wk,
                             const float* __restrict__ Wv, const float* __restrict__ We) {
    int t = blockIdx.x * blockDim.x + threadIdx.x;
    if (t >= 4 * 32768) return;
    int mat = t >> 15;
    int rem = t & 32767;
    int ks = rem >> 10;
    int nb = (rem >> 5) & 31;
    int tt = rem & 31;
    const float* W = mat == 0 ? Wq : mat == 1 ? Wk : mat == 2 ? Wv : We;
    int k = ks * 8 + (tt & 3);
    int n = nb * 8 + (tt >> 2);
    g_Btf[mat][rem * 2 + 0] = f2tf32(W[k * HD + n]);
    g_Btf[mat][rem * 2 + 1] = f2tf32(W[(k + 4) * HD + n]);
}

// ---------------------------------------------------------------------------
// A convert+store: thread r = tid>>2 (row), u = tid&3 (8-k unit); tf32 cvt.
// ---------------------------------------------------------------------------
__device__ __forceinline__ void convert_store_A(char* smem, int buf, int tid,
                                                float4 f0, float4 f1) {
    int r = tid >> 2, u = tid & 3;
    uint32_t c[8];
    c[0] = f2tf32(f0.x); c[1] = f2tf32(f0.y); c[2] = f2tf32(f0.z); c[3] = f2tf32(f0.w);
    c[4] = f2tf32(f1.x); c[5] = f2tf32(f1.y); c[6] = f2tf32(f1.z); c[7] = f2tf32(f1.w);
    char* base = smem + SM_A + buf * ABUF + r * A_STRIDE + u * 32;
    *(uint4*)(base)      = make_uint4(c[0], c[1], c[2], c[3]);
    *(uint4*)(base + 16) = make_uint4(c[4], c[5], c[6], c[7]);
}

// ---------------------------------------------------------------------------
// GEMM mainloop: acc[2][8][4] += tf32( A[m0:64, :256] @ W[0:256]^T )
// 256 threads, 8 warps (2 m x 4 n); warp tile 32 x 64. Double-buffered.
// ---------------------------------------------------------------------------
__device__ __forceinline__ void gemm_tile(char* smem, uint32_t sb,
                                          const float* __restrict__ A, int m0,
                                          int mat, int tid, float acc[2][8][4]) {
    int lane = tid & 31, w = tid >> 5;
    int warp_m = w & 1, warp_n = w >> 1;
    const char* Btf = (const char*)g_Btf[mat];
    int r = tid >> 2, u = tid & 3;

    // A fragment base offsets (within buffer): a0 at (arow + lane/4, col lane%4)
    uint32_t aFrag = (uint32_t)((warp_m * 32 + (lane >> 2)) * A_STRIDE + (lane & 3) * 4);
    // B fragment base (within buffer): block (ksl, nb = warp_n*8 + nf), 8B per lane
    uint32_t bFrag = (uint32_t)(((warp_n * 8) * 32 + lane) * 8);

    // prologue: chunk 0
    {
        const float4* src = (const float4*)(A + (size_t)(m0 + r) * DIN + u * 8);
        float4 f0 = src[0], f1 = src[1];
        #pragma unroll
        for (int i = 0; i < 8; ++i) {
            uint32_t off = (uint32_t)(tid + 256 * i) * 16;
            cp_async16(sb + SM_B + off, Btf + off);
        }
        CP_COMMIT;
        convert_store_A(smem, 0, tid, f0, f1);
        CP_WAIT0;
        __syncthreads();
    }

    for (int kc = 0; kc < 8; ++kc) {
        int cur = kc & 1, nxt = cur ^ 1;
        float4 f0, f1;
        if (kc < 7) {
            const float4* src = (const float4*)(A + (size_t)(m0 + r) * DIN + (kc + 1) * 32 + u * 8);
            f0 = src[0]; f1 = src[1];
            const char* bsrc = Btf + (size_t)(kc + 1) * BBUF;
            #pragma unroll
            for (int i = 0; i < 8; ++i) {
                uint32_t off = (uint32_t)(tid + 256 * i) * 16;
                cp_async16(sb + SM_B + nxt * BBUF + off, bsrc + off);
            }
            CP_COMMIT;
        }

        uint32_t aBase = sb + SM_A + cur * ABUF + aFrag;
        uint32_t bBase = sb + SM_B + cur * BBUF + bFrag;
        #pragma unroll
        for (int ksl = 0; ksl < 4; ++ksl) {
            uint32_t a[2][4];
            #pragma unroll
            for (int mf = 0; mf < 2; ++mf) {
                uint32_t ad = aBase + (uint32_t)(mf * 16 * A_STRIDE + ksl * 32);
                asm volatile("ld.shared.b32 %0, [%1];"      : "=r"(a[mf][0]) : "r"(ad));
                asm volatile("ld.shared.b32 %0, [%1];"      : "=r"(a[mf][1]) : "r"(ad + 8 * A_STRIDE));
                asm volatile("ld.shared.b32 %0, [%1];"      : "=r"(a[mf][2]) : "r"(ad + 16));
                asm volatile("ld.shared.b32 %0, [%1];"      : "=r"(a[mf][3]) : "r"(ad + 8 * A_STRIDE + 16));
            }
            #pragma unroll
            for (int nf = 0; nf < 8; ++nf) {
                uint32_t b[2];
                uint32_t bd = bBase + (uint32_t)((ksl * 32 + nf) * 256);
                asm volatile("ld.shared.v2.b32 {%0,%1}, [%2];" : "=r"(b[0]), "=r"(b[1]) : "r"(bd));
                mma_tf32(acc[0][nf], a[0], b);
                mma_tf32(acc[1][nf], a[1], b);
            }
        }

        if (kc < 7) {
            convert_store_A(smem, nxt, tid, f0, f1);
            CP_WAIT0;
            __syncthreads();
        }
    }
}

// ---------------------------------------------------------------------------
// QKV GEMM. grid (250, 3), 256 threads. CTA tile 64 x 256.
// ---------------------------------------------------------------------------
__global__ __launch_bounds__(256, 2) void qkv_mm(const float* __restrict__ x) {
    extern __shared__ char smem[];
    uint32_t sb = smem_u32(smem);
    int tid = threadIdx.x;
    int m0 = blockIdx.x * 64;
    int mat = blockIdx.y;

    float acc[2][8][4];
    #pragma unroll
    for (int mf = 0; mf < 2; ++mf)
        #pragma unroll
        for (int nf = 0; nf < 8; ++nf)
            #pragma unroll
            for (int p = 0; p < 4; ++p) acc[mf][nf][p] = 0.0f;

    gemm_tile(smem, sb, x, m0, mat, tid, acc);

    int lane = tid & 31, w = tid >> 5;
    int warp_m = w & 1, warp_n = w >> 1;
    int qrow = lane >> 2, qcol = lane & 3;
    float* out = mat == 0 ? g_q : mat == 1 ? g_k : g_v;

    #pragma unroll
    for (int mf = 0; mf < 2; ++mf) {
        int r0 = m0 + warp_m * 32 + mf * 16 + qrow;
        #pragma unroll
        for (int nf = 0; nf < 8; ++nf) {
            int c = warp_n * 64 + nf * 8 + qcol * 2;
            *(float2*)(out + (size_t)r0 * HD + c)       = make_float2(acc[mf][nf][0], acc[mf][nf][1]);
            *(float2*)(out + (size_t)(r0 + 8) * HD + c) = make_float2(acc[mf][nf][2], acc[mf][nf][3]);
        }
    }
}

// ---------------------------------------------------------------------------
// Edge GEMM + transposed fused epilogue. grid 4000, 256 threads.
// Each CTA: 64 edges x 256 cols (all 8 heads).
// ---------------------------------------------------------------------------
__global__ __launch_bounds__(256, 2) void edge_mm(const float* __restrict__ edge_attr,
                                                  const int* __restrict__ ei,
                                                  const float* __restrict__ coords,
                                                  const float* __restrict__ We,
                                                  float* __restrict__ eout) {
    extern __shared__ char smem[];
    uint32_t sb = smem_u32(smem);
    int tid = threadIdx.x;
    int m0 = blockIdx.x * 64;

    int*   sSrc = (int*)(smem + SM_SRC);
    int*   sDst = (int*)(smem + SM_DST);
    float* sDist = (float*)(smem + SM_DIST);

    if (tid < 64) {
        int s = ei[m0 + tid];
        int d = ei[NEDGES + m0 + tid];
        sSrc[tid] = s; sDst[tid] = d;
        float dx = coords[3 * s + 0] - coords[3 * d + 0];
        float dy = coords[3 * s + 1] - coords[3 * d + 1];
        float dz = coords[3 * s + 2] - coords[3 * d + 2];
        sDist[tid] = 0.1f * sqrtf(dx * dx + dy * dy + dz * dz);
    }
    __syncthreads();

    float acc[2][8][4];
    #pragma unroll
    for (int mf = 0; mf < 2; ++mf)
        #pragma unroll
        for (int nf = 0; nf < 8; ++nf)
            #pragma unroll
            for (int p = 0; p < 4; ++p) acc[mf][nf][p] = 0.0f;

    gemm_tile(smem, sb, edge_attr, m0, 3, tid, acc);

    int lane = tid & 31, w = tid >> 5;
    int warp_m = w & 1, warp_n = w >> 1;
    int qrow = lane >> 2, qcol = lane & 3;

    // ---- stage raw acc into smem alpha tile [64][264] (reuses A/B bufs) ----
    __syncthreads();
    float* alpha = (float*)(smem + SM_ALPHA);
    #pragma unroll
    for (int mf = 0; mf < 2; ++mf) {
        int r0 = warp_m * 32 + mf * 16 + qrow;
        #pragma unroll
        for (int nf = 0; nf < 8; ++nf) {
            int c = warp_n * 64 + nf * 8 + qcol * 2;
            *(float2*)&alpha[r0 * ALPHA_STRIDE + c]       = make_float2(acc[mf][nf][0], acc[mf][nf][1]);
            *(float2*)&alpha[(r0 + 8) * ALPHA_STRIDE + c] = make_float2(acc[mf][nf][2], acc[mf][nf][3]);
        }
    }
    __syncthreads();

    // ---- transposed epilogue: warp w handles edges w*8 .. w*8+7 ----
    const float invs = 0.17677669529663687f;   // 1/sqrt(32)
    int c0 = lane * 4;
    int c1 = 128 + lane * 4;
    int h0 = lane >> 3;
    float4 wlA = *(const float4*)(We + (size_t)DIN * HD + c0);
    float4 wlB = *(const float4*)(We + (size_t)DIN * HD + c1);

    #pragma unroll 2
    for (int i = 0; i < 8; ++i) {
        int e = w * 8 + i;
        int src = sSrc[e], dst = sDst[e];
        float de = sDist[e];
        const float* krow = g_k + (size_t)src * HD;
        const float* qrow_p = g_q + (size_t)dst * HD;
        float4 dA = *(const float4*)&alpha[e * ALPHA_STRIDE + c0];
        float4 dB = *(const float4*)&alpha[e * ALPHA_STRIDE + c1];
        float4 kA = *(const float4*)(krow + c0);
        float4 kB = *(const float4*)(krow + c1);
        float4 qA = *(const float4*)(qrow_p + c0);
        float4 qB = *(const float4*)(qrow_p + c1);
        float4 aA, aB;
        float s;
        s = fminf(5.0f, fmaxf(-5.0f, kA.x * qA.x * invs)); aA.x = s * (dA.x + de * wlA.x);
        s = fminf(5.0f, fmaxf(-5.0f, kA.y * qA.y * invs)); aA.y = s * (dA.y + de * wlA.y);
        s = fminf(5.0f, fmaxf(-5.0f, kA.z * qA.z * invs)); aA.z = s * (dA.z + de * wlA.z);
        s = fminf(5.0f, fmaxf(-5.0f, kA.w * qA.w * invs)); aA.w = s * (dA.w + de * wlA.w);
        s = fminf(5.0f, fmaxf(-5.0f, kB.x * qB.x * invs)); aB.x = s * (dB.x + de * wlB.x);
        s = fminf(5.0f, fmaxf(-5.0f, kB.y * qB.y * invs)); aB.y = s * (dB.y + de * wlB.y);
        s = fminf(5.0f, fmaxf(-5.0f, kB.z * qB.z * invs)); aB.z = s * (dB.z + de * wlB.z);
        s = fminf(5.0f, fmaxf(-5.0f, kB.w * qB.w * invs)); aB.w = s * (dB.w + de * wlB.w);
        float* eo = eout + (size_t)(m0 + e) * HD;
        *(float4*)(eo + c0) = aA;
        *(float4*)(eo + c1) = aB;

        float pA = (aA.x + aA.y) + (aA.z + aA.w);
        float pB = (aB.x + aB.y) + (aB.z + aB.w);
        pA += __shfl_xor_sync(0xffffffffu, pA, 1);
        pB += __shfl_xor_sync(0xffffffffu, pB, 1);
        pA += __shfl_xor_sync(0xffffffffu, pA, 2);
        pB += __shfl_xor_sync(0xffffffffu, pB, 2);
        pA += __shfl_xor_sync(0xffffffffu, pA, 4);
        pB += __shfl_xor_sync(0xffffffffu, pB, 4);
        float axA = expf(fminf(5.0f, fmaxf(-5.0f, pA)));
        float axB = expf(fminf(5.0f, fmaxf(-5.0f, pB)));

        const float* vrow = g_v + (size_t)src * HD;
        float4 vA = *(const float4*)(vrow + c0);
        float4 vB = *(const float4*)(vrow + c1);
        float* wv = g_wV + (size_t)dst * HD;
        atomicAdd(wv + c0 + 0, vA.x * axA);
        atomicAdd(wv + c0 + 1, vA.y * axA);
        atomicAdd(wv + c0 + 2, vA.z * axA);
        atomicAdd(wv + c0 + 3, vA.w * axA);
        atomicAdd(wv + c1 + 0, vB.x * axB);
        atomicAdd(wv + c1 + 1, vB.y * axB);
        atomicAdd(wv + c1 + 2, vB.z * axB);
        atomicAdd(wv + c1 + 3, vB.w * axB);
        if ((lane & 7) == 0) {
            atomicAdd(&g_z[(size_t)dst * NH + h0], axA);
            atomicAdd(&g_z[(size_t)dst * NH + 4 + h0], axB);
        }
    }
}

// ---------------------------------------------------------------------------
__global__ void finalize_kernel(float* __restrict__ hout) {
    int i = blockIdx.x * blockDim.x + threadIdx.x;
    if (i < NNODES * HD) {
        int n = i >> 8;
        int h = (i & 255) >> 5;
        hout[i] = g_wV[i] / (g_z[n * NH + h] + 1e-6f);
    }
}

// ---------------------------------------------------------------------------
extern "C" void kernel_launch(void* const* d_in, const int* in_sizes, int n_in,
                              void* d_out, int out_size)
{
    const float* x         = (const float*)d_in[0];
    const float* edge_attr = (const float*)d_in[1];
    const int*   ei        = (const int*)d_in[2];
    const float* coords    = (const float*)d_in[3];
    const float* Wq        = (const float*)d_in[4];
    const float* Wk        = (const float*)d_in[5];
    const float* Wv        = (const float*)d_in[6];
    const float* We        = (const float*)d_in[7];

    float* out  = (float*)d_out;
    float* hout = out;
    float* eout = out + (size_t)NNODES * HD;
    float* cout = eout + (size_t)NEDGES * HD;

    static bool attr_set = false;
    if (!attr_set) {
        cudaFuncSetAttribute(qkv_mm,  cudaFuncAttributeMaxDynamicSharedMemorySize, SM_TOTAL);
        cudaFuncSetAttribute(edge_mm, cudaFuncAttributeMaxDynamicSharedMemorySize, SM_TOTAL);
        attr_set = true;
    }

    zero_kernel<<<(NNODES * HD + 255) / 256, 256>>>(coords, cout);
    prep_weights<<<512, 256>>>(Wq, Wk, Wv, We);
    qkv_mm<<<dim3(250, 3), 256, SM_TOTAL>>>(x);
    edge_mm<<<4000, 256, SM_TOTAL>>>(edge_attr, ei, coords, We, eout);
    finalize_kernel<<<(NNODES * HD + 255) / 256, 256>>>(hout);
}